// round 2
// baseline (speedup 1.0000x reference)
#include <cuda_runtime.h>

typedef unsigned long long u64;

// ---- packed f32x2 helpers (ptxas only emits FFMA2 from PTX fma.rn.f32x2) ----
__device__ __forceinline__ u64 pk(float lo, float hi) {
    u64 r; asm("mov.b64 %0, {%1, %2};" : "=l"(r) : "f"(lo), "f"(hi)); return r;
}
__device__ __forceinline__ float2 upk(u64 v) {
    float2 f; asm("mov.b64 {%0, %1}, %2;" : "=f"(f.x), "=f"(f.y) : "l"(v)); return f;
}
__device__ __forceinline__ u64 fma2(u64 a, u64 b, u64 c) {
    u64 d; asm("fma.rn.f32x2 %0, %1, %2, %3;" : "=l"(d) : "l"(a), "l"(b), "l"(c)); return d;
}

// Each thread computes TWO rows (r0 = tid, r1 = tid + half) sharing one pass
// over the weights in shared memory, halving LDS traffic per row.
__global__ __launch_bounds__(256) void mlp_threshold_kernel(
    const float* __restrict__ x,
    const float* __restrict__ W1,   // [10,16] row-major
    const float* __restrict__ b1,   // [16]
    const float* __restrict__ W2,   // [16,1] -> 16 contiguous
    const float* __restrict__ b2,   // [1]
    const float* __restrict__ thr,  // [1]
    float* __restrict__ out,        // [B] (reversed order)
    int B, int half)
{
    // Packed weights: pair neurons (2p, 2p+1) into one f32x2.
    __shared__ u64 sW1[10][8];
    __shared__ u64 sB1[8];
    __shared__ u64 sW2[8];
    __shared__ float sB2, sThr;

    int t = threadIdx.x;
    if (t < 80) {
        int i = t >> 3, p = t & 7;
        sW1[i][p] = pk(W1[i * 16 + 2 * p], W1[i * 16 + 2 * p + 1]);
    } else if (t < 88) {
        int p = t - 80;
        sB1[p] = pk(b1[2 * p], b1[2 * p + 1]);
    } else if (t < 96) {
        int p = t - 88;
        sW2[p] = pk(W2[2 * p], W2[2 * p + 1]);
    } else if (t == 96) {
        sB2 = b2[0];
        sThr = thr[0];
    }
    __syncthreads();

    int r0 = blockIdx.x * 256 + t;
    if (r0 >= half) return;
    int r1 = r0 + half;
    bool has1 = (r1 < B);
    int r1c = has1 ? r1 : r0;   // redundant-but-safe second row for the tail

    // Load both input rows: 10 floats = 5 x float2 (40-byte rows are 8B aligned).
    float xa[10], xb[10];
    {
        const float2* p0 = reinterpret_cast<const float2*>(x + (size_t)r0 * 10);
        const float2* p1 = reinterpret_cast<const float2*>(x + (size_t)r1c * 10);
        #pragma unroll
        for (int k = 0; k < 5; k++) { float2 v = p0[k]; xa[2*k] = v.x; xa[2*k+1] = v.y; }
        #pragma unroll
        for (int k = 0; k < 5; k++) { float2 v = p1[k]; xb[2*k] = v.x; xb[2*k+1] = v.y; }
    }

    // fc1: 8 packed accumulators per row; one LDS.64 weight feeds both rows.
    u64 acc0[8], acc1[8];
    #pragma unroll
    for (int p = 0; p < 8; p++) { u64 b = sB1[p]; acc0[p] = b; acc1[p] = b; }

    #pragma unroll
    for (int i = 0; i < 10; i++) {
        u64 xp0 = pk(xa[i], xa[i]);
        u64 xp1 = pk(xb[i], xb[i]);
        #pragma unroll
        for (int p = 0; p < 8; p++) {
            u64 w = sW1[i][p];
            acc0[p] = fma2(xp0, w, acc0[p]);
            acc1[p] = fma2(xp1, w, acc1[p]);
        }
    }

    // relu + fc2 (packed dot with W2), then horizontal sum.
    u64 y0 = 0ull, y1 = 0ull;  // pk(0,0)
    #pragma unroll
    for (int p = 0; p < 8; p++) {
        float2 h0 = upk(acc0[p]);
        float2 h1 = upk(acc1[p]);
        h0.x = fmaxf(h0.x, 0.0f); h0.y = fmaxf(h0.y, 0.0f);
        h1.x = fmaxf(h1.x, 0.0f); h1.y = fmaxf(h1.y, 0.0f);
        u64 w2 = sW2[p];
        y0 = fma2(pk(h0.x, h0.y), w2, y0);
        y1 = fma2(pk(h1.x, h1.y), w2, y1);
    }
    float2 s0 = upk(y0), s1 = upk(y1);
    float bb = sB2, tt = sThr;
    float ya = fmaxf(s0.x + s0.y + bb, 0.0f);
    float yb = fmaxf(s1.x + s1.y + bb, 0.0f);

    // Threshold: y >= 0 so trunc == floor; jnp.round == rint (half-to-even).
    float fa = floorf(ya); float da = ya - fa;
    float oa = (da > tt) ? rintf(ya) : fa;
    float fb = floorf(yb); float db = yb - fb;
    float ob = (db > tt) ? rintf(yb) : fb;

    // Output order is reversed: out[B-1-row] = result(row). Still coalesced.
    out[(size_t)(B - 1) - (size_t)r0] = oa;
    if (has1) out[(size_t)(B - 1) - (size_t)r1] = ob;
}

extern "C" void kernel_launch(void* const* d_in, const int* in_sizes, int n_in,
                              void* d_out, int out_size) {
    const float* x   = (const float*)d_in[0];
    const float* W1  = (const float*)d_in[1];
    const float* b1  = (const float*)d_in[2];
    const float* W2  = (const float*)d_in[3];
    const float* b2  = (const float*)d_in[4];
    const float* thr = (const float*)d_in[5];
    float* out = (float*)d_out;

    int B = out_size;                 // rows (out is [B,1])
    int half = (B + 1) / 2;           // two rows per thread
    int blocks = (half + 255) / 256;
    mlp_threshold_kernel<<<blocks, 256>>>(x, W1, b1, W2, b2, thr, out, B, half);
}

// round 3
// speedup vs baseline: 1.0833x; 1.0833x over previous
#include <cuda_runtime.h>

typedef unsigned long long u64;

static constexpr int TPB        = 256;
static constexpr int TILE_PAIRS = 256;             // row-pairs per tile (= TPB)
static constexpr int TILE_BYTES = TILE_PAIRS * 80; // 20480 (pair = 2 rows * 40B)
static constexpr int MAX_GRID   = 444;             // ~3 blocks/SM persistent

// ---- packed f32x2 helpers (ptxas only emits FFMA2 from PTX fma.rn.f32x2) ----
__device__ __forceinline__ u64 pk(float lo, float hi) {
    u64 r; asm("mov.b64 %0, {%1, %2};" : "=l"(r) : "f"(lo), "f"(hi)); return r;
}
__device__ __forceinline__ float2 upk(u64 v) {
    float2 f; asm("mov.b64 {%0, %1}, %2;" : "=f"(f.x), "=f"(f.y) : "l"(v)); return f;
}
__device__ __forceinline__ u64 fma2(u64 a, u64 b, u64 c) {
    u64 d; asm("fma.rn.f32x2 %0, %1, %2, %3;" : "=l"(d) : "l"(a), "l"(b), "l"(c)); return d;
}
__device__ __forceinline__ unsigned s2u(const void* p) {
    unsigned a;
    asm("{ .reg .u64 t; cvta.to.shared.u64 t, %1; cvt.u32.u64 %0, t; }" : "=r"(a) : "l"(p));
    return a;
}
__device__ __forceinline__ void cp16(unsigned dst, const void* src, int pred) {
    asm volatile("{ .reg .pred p; setp.ne.b32 p, %2, 0;"
                 " @p cp.async.cg.shared.global [%0], [%1], 16; }"
                 :: "r"(dst), "l"(src), "r"(pred));
}
__device__ __forceinline__ void cpcommit() {
    asm volatile("cp.async.commit_group;" ::: "memory");
}
template<int N> __device__ __forceinline__ void cpwait() {
    asm volatile("cp.async.wait_group %0;" :: "n"(N) : "memory");
}

__global__ __launch_bounds__(TPB) void mlp_threshold_kernel(
    const float* __restrict__ x,
    const float* __restrict__ W1,   // [10,16] row-major
    const float* __restrict__ b1,   // [16]
    const float* __restrict__ W2,   // [16]
    const float* __restrict__ b2,   // [1]
    const float* __restrict__ thr,  // [1]
    float* __restrict__ out,        // [B] (reversed order)
    int B, int pairs, int ntiles)
{
    __shared__ char sx[2][TILE_BYTES];
    __shared__ u64 sW1[10][8];
    __shared__ u64 sB1[8];
    __shared__ u64 sW2[8];
    __shared__ float sB2, sThr;

    const int t = threadIdx.x;

    // ---- load weights (packed neuron pairs) into smem ----
    if (t < 80) {
        int i = t >> 3, p = t & 7;
        sW1[i][p] = pk(W1[i * 16 + 2 * p], W1[i * 16 + 2 * p + 1]);
    } else if (t < 88) {
        int p = t - 80;
        sB1[p] = pk(b1[2 * p], b1[2 * p + 1]);
    } else if (t < 96) {
        int p = t - 88;
        sW2[p] = pk(W2[2 * p], W2[2 * p + 1]);
    } else if (t == 96) {
        sB2 = b2[0];
        sThr = thr[0];
    }

    const char* xb = (const char*)x;
    const long long total_chunks = (long long)pairs * 5;  // 16B chunks of x

    // ---- stage one tile into buffer `buf` via coalesced cp.async ----
    auto stage = [&](int buf, int tile) {
        unsigned sdst = s2u(&sx[buf][0]);
        long long c0 = (long long)tile * (TILE_PAIRS * 5);
        #pragma unroll
        for (int j = 0; j < 5; j++) {
            long long c = c0 + t + j * TPB;       // consecutive t -> consecutive 16B
            cp16(sdst + (unsigned)(t + j * TPB) * 16u, xb + c * 16, (int)(c < total_chunks));
        }
    };

    int tile = blockIdx.x;
    if (tile < ntiles) stage(0, tile);
    cpcommit();

    int cur = 0;
    for (; tile < ntiles; tile += gridDim.x) {
        int nxt = tile + gridDim.x;
        bool more = (nxt < ntiles);
        if (more) stage(cur ^ 1, nxt);
        cpcommit();
        if (more) cpwait<1>(); else cpwait<0>();
        __syncthreads();   // cp.async data for sx[cur] + (first iter) weights visible

        // ---- compute: pair q = rows (2q, 2q+1), 80B contiguous in smem ----
        int q = tile * TILE_PAIRS + t;
        bool active = (q < pairs);

        float xa[10], xbv[10];
        {
            const float2* f2 = (const float2*)&sx[cur][t * 80];
            #pragma unroll
            for (int k = 0; k < 5; k++) { float2 v = f2[k];     xa[2*k] = v.x; xa[2*k+1] = v.y; }
            #pragma unroll
            for (int k = 0; k < 5; k++) { float2 v = f2[5 + k]; xbv[2*k] = v.x; xbv[2*k+1] = v.y; }
        }

        u64 acc0[8], acc1[8];
        #pragma unroll
        for (int p = 0; p < 8; p++) { u64 b = sB1[p]; acc0[p] = b; acc1[p] = b; }

        #pragma unroll
        for (int i = 0; i < 10; i++) {
            u64 xp0 = pk(xa[i], xa[i]);
            u64 xp1 = pk(xbv[i], xbv[i]);
            #pragma unroll
            for (int p = 0; p < 8; p++) {
                u64 w = sW1[i][p];          // broadcast LDS.64 serves both rows
                acc0[p] = fma2(xp0, w, acc0[p]);
                acc1[p] = fma2(xp1, w, acc1[p]);
            }
        }

        u64 y0 = 0ull, y1 = 0ull;
        #pragma unroll
        for (int p = 0; p < 8; p++) {
            float2 h0 = upk(acc0[p]);
            float2 h1 = upk(acc1[p]);
            h0.x = fmaxf(h0.x, 0.0f); h0.y = fmaxf(h0.y, 0.0f);
            h1.x = fmaxf(h1.x, 0.0f); h1.y = fmaxf(h1.y, 0.0f);
            u64 w2 = sW2[p];
            y0 = fma2(pk(h0.x, h0.y), w2, y0);
            y1 = fma2(pk(h1.x, h1.y), w2, y1);
        }
        float2 s0 = upk(y0), s1 = upk(y1);
        float bb = sB2, tt = sThr;
        float ya = fmaxf(s0.x + s0.y + bb, 0.0f);   // row 2q
        float yb = fmaxf(s1.x + s1.y + bb, 0.0f);   // row 2q+1

        // y >= 0 so trunc == floor; jnp.round == rint (half-to-even).
        float fa = floorf(ya); float oa = (ya - fa > tt) ? rintf(ya) : fa;
        float fb = floorf(yb); float ob = (yb - fb > tt) ? rintf(yb) : fb;

        if (active) {
            // out[B-1-2q] = oa, out[B-2-2q] = ob -> one aligned STG.64
            float2 o; o.x = ob; o.y = oa;
            *reinterpret_cast<float2*>(out + (B - 2 - 2 * q)) = o;
        }
        __syncthreads();   // done reading sx[cur] before it gets restaged
        cur ^= 1;
    }

    // odd-B tail: one leftover row handled scalar (B is even in practice)
    if ((B & 1) && blockIdx.x == 0 && threadIdx.x == 0) {
        int r = B - 1;
        float h[16];
        #pragma unroll
        for (int n = 0; n < 16; n++) h[n] = b1[n];
        for (int i = 0; i < 10; i++) {
            float xv = x[(size_t)r * 10 + i];
            #pragma unroll
            for (int n = 0; n < 16; n++) h[n] = fmaf(xv, W1[i * 16 + n], h[n]);
        }
        float y = b2[0];
        #pragma unroll
        for (int n = 0; n < 16; n++) y = fmaf(fmaxf(h[n], 0.0f), W2[n], y);
        y = fmaxf(y, 0.0f);
        float fy = floorf(y);
        out[0] = (y - fy > thr[0]) ? rintf(y) : fy;
    }
}

extern "C" void kernel_launch(void* const* d_in, const int* in_sizes, int n_in,
                              void* d_out, int out_size) {
    const float* x   = (const float*)d_in[0];
    const float* W1  = (const float*)d_in[1];
    const float* b1  = (const float*)d_in[2];
    const float* W2  = (const float*)d_in[3];
    const float* b2  = (const float*)d_in[4];
    const float* thr = (const float*)d_in[5];
    float* out = (float*)d_out;

    int B = out_size;
    int pairs = B >> 1;
    int ntiles = (pairs + TILE_PAIRS - 1) / TILE_PAIRS;
    int grid = ntiles < MAX_GRID ? (ntiles > 0 ? ntiles : 1) : MAX_GRID;
    mlp_threshold_kernel<<<grid, TPB>>>(x, W1, b1, W2, b2, thr, out, B, pairs, ntiles);
}